// round 14
// baseline (speedup 1.0000x reference)
#include <cuda_runtime.h>
#include <math.h>
#include <stdint.h>

#define REF_Y 0.5f
#define EPSF  1e-08f

#define NTHR  1024
#define NWARP (NTHR / 32)        // 32

__global__ __launch_bounds__(NTHR, 1)
void lamse_kernel(const float* __restrict__ x,
                  const float* __restrict__ t,
                  float* __restrict__ out,
                  int n) {
    // sh[k][w]: sum k from warp w; 33-stride padding keeps warp-0's
    // gather (lane l reads sh[k][l]) conflict-free
    __shared__ float sh[5][33];

    const int tid = threadIdx.x;
    const int wid = tid >> 5;
    const int lid = tid & 31;

    const int n4 = n >> 2;
    const float4* __restrict__ x4 = (const float4*)x;
    const float4* __restrict__ t4 = (const float4*)t;

    // ---- issue all vector loads first (4 LDG.128 in flight per thread) ----
    const int i0 = tid;
    const int i1 = tid + NTHR;
    bool h0 = i0 < n4, h1 = i1 < n4;
    float4 xa, ta, xb, tb;
    if (h0) { xa = x4[i0]; ta = t4[i0]; }
    if (h1) { xb = x4[i1]; tb = t4[i1]; }

    // ---- per-thread accumulation (5 sums; inputs are NaN-free normals) ----
    float s_w = 0.f, s_e = 0.f, s_ew = 0.f, s_e2 = 0.f, s_e2w = 0.f;

    #define PROC(xj, tj) do {                                            \
        float _w = __fdividef(fabsf(REF_Y - (tj)),                       \
                              fabsf(REF_Y) + fabsf(tj) + EPSF);          \
        _w = fminf(fmaxf(_w, 0.1f), 2.0f);                               \
        float _e = (xj) - (tj);                                          \
        s_w  += _w;                                                      \
        s_e  += _e;                                                      \
        s_ew  = fmaf(_e, _w, s_ew);                                      \
        s_e2  = fmaf(_e, _e, s_e2);                                      \
        s_e2w = fmaf(_e * _e, _w, s_e2w);                                \
    } while (0)

    if (h0) { PROC(xa.x, ta.x); PROC(xa.y, ta.y); PROC(xa.z, ta.z); PROC(xa.w, ta.w); }
    if (h1) { PROC(xb.x, tb.x); PROC(xb.y, tb.y); PROC(xb.z, tb.z); PROC(xb.w, tb.w); }
    // generic residue (not taken for n=8192)
    for (int i = tid + 2 * NTHR; i < n4; i += NTHR) {
        float4 a = x4[i], b = t4[i];
        PROC(a.x, b.x); PROC(a.y, b.y); PROC(a.z, b.z); PROC(a.w, b.w);
    }
    for (int i = (n4 << 2) + tid; i < n; i += NTHR) {
        float xj = x[i], tj = t[i];
        PROC(xj, tj);
    }
    #undef PROC

    // ---- warp shuffle reduce (5 sums, 5 levels) ----
    #pragma unroll
    for (int off = 16; off > 0; off >>= 1) {
        s_w   += __shfl_down_sync(0xffffffffu, s_w,   off);
        s_e   += __shfl_down_sync(0xffffffffu, s_e,   off);
        s_ew  += __shfl_down_sync(0xffffffffu, s_ew,  off);
        s_e2  += __shfl_down_sync(0xffffffffu, s_e2,  off);
        s_e2w += __shfl_down_sync(0xffffffffu, s_e2w, off);
    }

    if (lid == 0) {
        sh[0][wid] = s_w;  sh[1][wid] = s_e;  sh[2][wid] = s_ew;
        sh[3][wid] = s_e2; sh[4][wid] = s_e2w;
    }
    __syncthreads();
    if (wid != 0) return;

    // ---- warp 0: lane l takes warp l's partials (conflict-free LDS) ----
    float v0 = sh[0][lid];
    float v1 = sh[1][lid];
    float v2 = sh[2][lid];
    float v3 = sh[3][lid];
    float v4 = sh[4][lid];
    #pragma unroll
    for (int off = 16; off > 0; off >>= 1) {
        v0 += __shfl_down_sync(0xffffffffu, v0, off);
        v1 += __shfl_down_sync(0xffffffffu, v1, off);
        v2 += __shfl_down_sync(0xffffffffu, v2, off);
        v3 += __shfl_down_sync(0xffffffffu, v3, off);
        v4 += __shfl_down_sync(0xffffffffu, v4, off);
    }

    if (lid == 0) {
        float S_w = v0, S_e = v1, S_ew = v2, S_e2 = v3, S_e2w = v4;
        float fn = (float)n;

        // mse (no NaNs => masked sums equal unmasked sums)
        float mse = __fdividef(S_e2w, S_w);

        // pairwise contrastive collapses to O(1):
        // num = 0.5*(n*Σe²w − 2*Σe*Σew + Σw*Σe²), den = 0.5*(n−1)*Σw
        float num = 0.5f * (fn * S_e2w - 2.0f * S_e * S_ew + S_w * S_e2);
        float den = 0.5f * (fn - 1.0f) * S_w;
        float c = __fdividef(num, den);

        // scale branch: c*(mse/c) == mse when taken
        bool do_scale = (c > EPSF) && (mse > EPSF) && (c < mse);
        float cs = do_scale ? mse : c;

        out[0] = 0.5f * (mse + cs);
    }
}

extern "C" void kernel_launch(void* const* d_in, const int* in_sizes, int n_in,
                              void* d_out, int out_size) {
    const float* x = (const float*)d_in[0];
    const float* t = (const float*)d_in[1];
    float* out = (float*)d_out;
    int n = in_sizes[0];
    lamse_kernel<<<1, NTHR>>>(x, t, out, n);
}

// round 15
// speedup vs baseline: 1.0047x; 1.0047x over previous
#include <cuda_runtime.h>
#include <math.h>
#include <stdint.h>

#define REF_Y 0.5f
#define EPSF  1e-08f

#define NBLK  4
#define NTHR  256
#define NWARP (NTHR / 32)        // 8

// cross-CTA scratch (zero-initialized; flags consumed-then-reset each replay)
__device__ float4   g_pa[NBLK];     // (Σw, Σe, Σew, Σe2)
__device__ float    g_pb[NBLK];     // Σe2w
__device__ unsigned g_flag[NBLK];

__global__ __launch_bounds__(NTHR, 1)
void lamse_kernel(const float* __restrict__ x,
                  const float* __restrict__ t,
                  float* __restrict__ out,
                  int n) {
    __shared__ float sh[NWARP][8];

    const int tid = threadIdx.x;
    const int wid = tid >> 5;
    const int lid = tid & 31;
    const int cta = blockIdx.x;

    const int n4     = n >> 2;
    const int stride = NBLK * NTHR;      // 1024
    const int gt     = cta * NTHR + tid;

    const float4* __restrict__ x4 = (const float4*)x;
    const float4* __restrict__ t4 = (const float4*)t;

    // ---- issue all vector loads first (4 LDG.128 in flight per thread) ----
    const int i0 = gt;
    const int i1 = gt + stride;
    bool h0 = i0 < n4, h1 = i1 < n4;
    float4 xa, ta, xb, tb;
    if (h0) { xa = x4[i0]; ta = t4[i0]; }
    if (h1) { xb = x4[i1]; tb = t4[i1]; }

    // ---- per-thread accumulation (5 sums; inputs are NaN-free normals) ----
    float s_w = 0.f, s_e = 0.f, s_ew = 0.f, s_e2 = 0.f, s_e2w = 0.f;

    #define PROC(xj, tj) do {                                            \
        float _w = __fdividef(fabsf(REF_Y - (tj)),                       \
                              fabsf(REF_Y) + fabsf(tj) + EPSF);          \
        _w = fminf(fmaxf(_w, 0.1f), 2.0f);                               \
        float _e = (xj) - (tj);                                          \
        s_w  += _w;                                                      \
        s_e  += _e;                                                      \
        s_ew  = fmaf(_e, _w, s_ew);                                      \
        s_e2  = fmaf(_e, _e, s_e2);                                      \
        s_e2w = fmaf(_e * _e, _w, s_e2w);                                \
    } while (0)

    if (h0) { PROC(xa.x, ta.x); PROC(xa.y, ta.y); PROC(xa.z, ta.z); PROC(xa.w, ta.w); }
    if (h1) { PROC(xb.x, tb.x); PROC(xb.y, tb.y); PROC(xb.z, tb.z); PROC(xb.w, tb.w); }
    // generic residue (not taken for n=8192)
    for (int i = gt + 2 * stride; i < n4; i += stride) {
        float4 a = x4[i], b = t4[i];
        PROC(a.x, b.x); PROC(a.y, b.y); PROC(a.z, b.z); PROC(a.w, b.w);
    }
    for (int i = (n4 << 2) + gt; i < n; i += stride) {
        float xj = x[i], tj = t[i];
        PROC(xj, tj);
    }
    #undef PROC

    // ---- warp shuffle reduce (5 sums, 5 levels) ----
    #pragma unroll
    for (int off = 16; off > 0; off >>= 1) {
        s_w   += __shfl_down_sync(0xffffffffu, s_w,   off);
        s_e   += __shfl_down_sync(0xffffffffu, s_e,   off);
        s_ew  += __shfl_down_sync(0xffffffffu, s_ew,  off);
        s_e2  += __shfl_down_sync(0xffffffffu, s_e2,  off);
        s_e2w += __shfl_down_sync(0xffffffffu, s_e2w, off);
    }

    if (lid == 0) {
        sh[wid][0] = s_w;  sh[wid][1] = s_e;  sh[wid][2] = s_ew;
        sh[wid][3] = s_e2; sh[wid][4] = s_e2w;
    }
    __syncthreads();
    if (wid != 0) return;

    // combine 8 warps (lanes 0..7, 3 shuffle levels)
    float v0 = (lid < NWARP) ? sh[lid][0] : 0.f;
    float v1 = (lid < NWARP) ? sh[lid][1] : 0.f;
    float v2 = (lid < NWARP) ? sh[lid][2] : 0.f;
    float v3 = (lid < NWARP) ? sh[lid][3] : 0.f;
    float v4 = (lid < NWARP) ? sh[lid][4] : 0.f;
    #pragma unroll
    for (int off = 4; off > 0; off >>= 1) {
        v0 += __shfl_down_sync(0xffffffffu, v0, off);
        v1 += __shfl_down_sync(0xffffffffu, v1, off);
        v2 += __shfl_down_sync(0xffffffffu, v2, off);
        v3 += __shfl_down_sync(0xffffffffu, v3, off);
        v4 += __shfl_down_sync(0xffffffffu, v4, off);
    }

    if (cta != 0) {
        // publish partials, then release-store flag
        if (lid == 0) {
            g_pa[cta] = make_float4(v0, v1, v2, v3);
            g_pb[cta] = v4;
            asm volatile("st.release.gpu.global.u32 [%0], %1;"
                         :: "l"(&g_flag[cta]), "r"(1u) : "memory");
        }
        return;
    }

    // ---- CTA 0 warp 0: lanes 1..3 acquire remote partials; lane 0 = own ----
    float w0 = 0.f, w1 = 0.f, w2 = 0.f, w3 = 0.f, w4 = 0.f;
    if (lid == 0) { w0 = v0; w1 = v1; w2 = v2; w3 = v3; w4 = v4; }
    if (lid >= 1 && lid < NBLK) {
        unsigned f;
        do {
            asm volatile("ld.acquire.gpu.global.u32 %0, [%1];"
                         : "=r"(f) : "l"(&g_flag[lid]) : "memory");
        } while (f == 0u);
        float4 a = g_pa[lid];
        float  b = g_pb[lid];
        w0 = a.x; w1 = a.y; w2 = a.z; w3 = a.w; w4 = b;
        g_flag[lid] = 0u;   // reset for next graph replay (serialized)
    }
    __syncwarp();

    #pragma unroll
    for (int off = 2; off > 0; off >>= 1) {
        w0 += __shfl_down_sync(0xffffffffu, w0, off);
        w1 += __shfl_down_sync(0xffffffffu, w1, off);
        w2 += __shfl_down_sync(0xffffffffu, w2, off);
        w3 += __shfl_down_sync(0xffffffffu, w3, off);
        w4 += __shfl_down_sync(0xffffffffu, w4, off);
    }

    if (lid == 0) {
        float S_w = w0, S_e = w1, S_ew = w2, S_e2 = w3, S_e2w = w4;
        float fn = (float)n;

        // mse (no NaNs => masked sums equal unmasked sums)
        float mse = __fdividef(S_e2w, S_w);

        // pairwise contrastive collapses to O(1):
        // num = 0.5*(n*Σe²w − 2*Σe*Σew + Σw*Σe²), den = 0.5*(n−1)*Σw
        float num = 0.5f * (fn * S_e2w - 2.0f * S_e * S_ew + S_w * S_e2);
        float den = 0.5f * (fn - 1.0f) * S_w;
        float c = __fdividef(num, den);

        // scale branch: c*(mse/c) == mse when taken
        bool do_scale = (c > EPSF) && (mse > EPSF) && (c < mse);
        float cs = do_scale ? mse : c;

        out[0] = 0.5f * (mse + cs);
    }
}

extern "C" void kernel_launch(void* const* d_in, const int* in_sizes, int n_in,
                              void* d_out, int out_size) {
    const float* x = (const float*)d_in[0];
    const float* t = (const float*)d_in[1];
    float* out = (float*)d_out;
    int n = in_sizes[0];
    lamse_kernel<<<NBLK, NTHR>>>(x, t, out, n);
}

// round 16
// speedup vs baseline: 1.0435x; 1.0386x over previous
#include <cuda_runtime.h>
#include <math.h>
#include <stdint.h>

#define REF_Y 0.5f
#define EPSF  1e-08f

#define NBLK  4
#define NTHR  256
#define NWARP (NTHR / 32)        // 8

// cross-CTA scratch (zero-initialized; flags consumed-then-reset each replay)
__device__ float4   g_pa[NBLK];     // (Σw, Σe, Σew, Σe2)
__device__ float    g_pb[NBLK];     // Σe2w
__device__ unsigned g_flag[NBLK];

__device__ __forceinline__ float weight_of(float tj) {
    float w = __fdividef(fabsf(REF_Y - tj), fabsf(REF_Y) + fabsf(tj) + EPSF);
    return fminf(fmaxf(w, 0.1f), 2.0f);
}

__global__ __launch_bounds__(NTHR, 1)
void lamse_kernel(const float* __restrict__ x,
                  const float* __restrict__ t,
                  float* __restrict__ out,
                  int n) {
    __shared__ float sh[NWARP][8];

    const int tid = threadIdx.x;
    const int wid = tid >> 5;
    const int lid = tid & 31;
    const int cta = blockIdx.x;

    const int n4     = n >> 2;
    const int stride = NBLK * NTHR;      // 1024
    const int gt     = cta * NTHR + tid;

    const float4* __restrict__ x4 = (const float4*)x;
    const float4* __restrict__ t4 = (const float4*)t;

    // ---- issue all vector loads first (4 LDG.128 in flight per thread) ----
    const int i0 = gt;
    const int i1 = gt + stride;
    bool h0 = i0 < n4, h1 = i1 < n4;
    float4 xa, ta, xb, tb;
    if (h0) { xa = x4[i0]; ta = t4[i0]; }
    if (h1) { xb = x4[i1]; tb = t4[i1]; }

    // ---- packed f32x2 accumulators (sm_103a FFMA2 pipe, PTX-only) ----
    unsigned long long a_w = 0ull, a_e = 0ull, a_ew = 0ull,
                       a_e2 = 0ull, a_e2w = 0ull;   // 0ull == packed (0.f, 0.f)

    // process two elements per packed step
    #define PROC2(x0, t0, x1, t1) do {                                       \
        float _w0 = weight_of(t0);                                           \
        float _w1 = weight_of(t1);                                           \
        float _e0 = (x0) - (t0);                                             \
        float _e1 = (x1) - (t1);                                             \
        unsigned long long _pe, _pw, _pe2;                                   \
        asm("mov.b64 %0, {%1, %2};" : "=l"(_pe) : "f"(_e0), "f"(_e1));       \
        asm("mov.b64 %0, {%1, %2};" : "=l"(_pw) : "f"(_w0), "f"(_w1));       \
        asm("add.rn.f32x2 %0, %0, %1;"     : "+l"(a_w)   : "l"(_pw));        \
        asm("add.rn.f32x2 %0, %0, %1;"     : "+l"(a_e)   : "l"(_pe));        \
        asm("fma.rn.f32x2 %0, %1, %2, %0;" : "+l"(a_ew)  : "l"(_pe), "l"(_pw)); \
        asm("fma.rn.f32x2 %0, %1, %1, %0;" : "+l"(a_e2)  : "l"(_pe));        \
        asm("mul.rn.f32x2 %0, %1, %1;"     : "=l"(_pe2)  : "l"(_pe));        \
        asm("fma.rn.f32x2 %0, %1, %2, %0;" : "+l"(a_e2w) : "l"(_pe2), "l"(_pw)); \
    } while (0)

    if (h0) { PROC2(xa.x, ta.x, xa.y, ta.y); PROC2(xa.z, ta.z, xa.w, ta.w); }
    if (h1) { PROC2(xb.x, tb.x, xb.y, tb.y); PROC2(xb.z, tb.z, xb.w, tb.w); }
    // generic residue (not taken for n=8192)
    for (int i = gt + 2 * stride; i < n4; i += stride) {
        float4 a = x4[i], b = t4[i];
        PROC2(a.x, b.x, a.y, b.y); PROC2(a.z, b.z, a.w, b.w);
    }
    #undef PROC2

    // unpack packed accumulators -> scalar sums
    float s_w, s_e, s_ew, s_e2, s_e2w;
    {
        float lo, hi;
        asm("mov.b64 {%0, %1}, %2;" : "=f"(lo), "=f"(hi) : "l"(a_w));   s_w   = lo + hi;
        asm("mov.b64 {%0, %1}, %2;" : "=f"(lo), "=f"(hi) : "l"(a_e));   s_e   = lo + hi;
        asm("mov.b64 {%0, %1}, %2;" : "=f"(lo), "=f"(hi) : "l"(a_ew));  s_ew  = lo + hi;
        asm("mov.b64 {%0, %1}, %2;" : "=f"(lo), "=f"(hi) : "l"(a_e2));  s_e2  = lo + hi;
        asm("mov.b64 {%0, %1}, %2;" : "=f"(lo), "=f"(hi) : "l"(a_e2w)); s_e2w = lo + hi;
    }
    // scalar residue (not taken for n=8192)
    for (int i = (n4 << 2) + gt; i < n; i += stride) {
        float xj = x[i], tj = t[i];
        float w = weight_of(tj);
        float e = xj - tj;
        s_w += w; s_e += e;
        s_ew = fmaf(e, w, s_ew);
        s_e2 = fmaf(e, e, s_e2);
        s_e2w = fmaf(e * e, w, s_e2w);
    }

    // ---- warp shuffle reduce (5 sums, 5 levels) ----
    #pragma unroll
    for (int off = 16; off > 0; off >>= 1) {
        s_w   += __shfl_down_sync(0xffffffffu, s_w,   off);
        s_e   += __shfl_down_sync(0xffffffffu, s_e,   off);
        s_ew  += __shfl_down_sync(0xffffffffu, s_ew,  off);
        s_e2  += __shfl_down_sync(0xffffffffu, s_e2,  off);
        s_e2w += __shfl_down_sync(0xffffffffu, s_e2w, off);
    }

    if (lid == 0) {
        sh[wid][0] = s_w;  sh[wid][1] = s_e;  sh[wid][2] = s_ew;
        sh[wid][3] = s_e2; sh[wid][4] = s_e2w;
    }
    __syncthreads();
    if (wid != 0) return;

    // combine 8 warps (lanes 0..7, 3 shuffle levels)
    float v0 = (lid < NWARP) ? sh[lid][0] : 0.f;
    float v1 = (lid < NWARP) ? sh[lid][1] : 0.f;
    float v2 = (lid < NWARP) ? sh[lid][2] : 0.f;
    float v3 = (lid < NWARP) ? sh[lid][3] : 0.f;
    float v4 = (lid < NWARP) ? sh[lid][4] : 0.f;
    #pragma unroll
    for (int off = 4; off > 0; off >>= 1) {
        v0 += __shfl_down_sync(0xffffffffu, v0, off);
        v1 += __shfl_down_sync(0xffffffffu, v1, off);
        v2 += __shfl_down_sync(0xffffffffu, v2, off);
        v3 += __shfl_down_sync(0xffffffffu, v3, off);
        v4 += __shfl_down_sync(0xffffffffu, v4, off);
    }

    if (cta != 0) {
        // publish partials, then release-store flag
        if (lid == 0) {
            g_pa[cta] = make_float4(v0, v1, v2, v3);
            g_pb[cta] = v4;
            asm volatile("st.release.gpu.global.u32 [%0], %1;"
                         :: "l"(&g_flag[cta]), "r"(1u) : "memory");
        }
        return;
    }

    // ---- CTA 0 warp 0: lanes 1..3 acquire remote partials; lane 0 = own ----
    float w0 = 0.f, w1 = 0.f, w2 = 0.f, w3 = 0.f, w4 = 0.f;
    if (lid == 0) { w0 = v0; w1 = v1; w2 = v2; w3 = v3; w4 = v4; }
    if (lid >= 1 && lid < NBLK) {
        unsigned f;
        do {
            asm volatile("ld.acquire.gpu.global.u32 %0, [%1];"
                         : "=r"(f) : "l"(&g_flag[lid]) : "memory");
        } while (f == 0u);
        float4 a = g_pa[lid];
        float  b = g_pb[lid];
        w0 = a.x; w1 = a.y; w2 = a.z; w3 = a.w; w4 = b;
        g_flag[lid] = 0u;   // reset for next graph replay (serialized)
    }
    __syncwarp();

    #pragma unroll
    for (int off = 2; off > 0; off >>= 1) {
        w0 += __shfl_down_sync(0xffffffffu, w0, off);
        w1 += __shfl_down_sync(0xffffffffu, w1, off);
        w2 += __shfl_down_sync(0xffffffffu, w2, off);
        w3 += __shfl_down_sync(0xffffffffu, w3, off);
        w4 += __shfl_down_sync(0xffffffffu, w4, off);
    }

    if (lid == 0) {
        float S_w = w0, S_e = w1, S_ew = w2, S_e2 = w3, S_e2w = w4;
        float fn = (float)n;

        // mse (no NaNs => masked sums equal unmasked sums)
        float mse = __fdividef(S_e2w, S_w);

        // pairwise contrastive collapses to O(1):
        // num = 0.5*(n*Σe²w − 2*Σe*Σew + Σw*Σe²), den = 0.5*(n−1)*Σw
        float num = 0.5f * (fn * S_e2w - 2.0f * S_e * S_ew + S_w * S_e2);
        float den = 0.5f * (fn - 1.0f) * S_w;
        float c = __fdividef(num, den);

        // scale branch: c*(mse/c) == mse when taken
        bool do_scale = (c > EPSF) && (mse > EPSF) && (c < mse);
        float cs = do_scale ? mse : c;

        out[0] = 0.5f * (mse + cs);
    }
}

extern "C" void kernel_launch(void* const* d_in, const int* in_sizes, int n_in,
                              void* d_out, int out_size) {
    const float* x = (const float*)d_in[0];
    const float* t = (const float*)d_in[1];
    float* out = (float*)d_out;
    int n = in_sizes[0];
    lamse_kernel<<<NBLK, NTHR>>>(x, t, out, n);
}